// round 11
// baseline (speedup 1.0000x reference)
#include <cuda_runtime.h>
#include <stdint.h>

#define NLAYERS 32
#define NPAR (NLAYERS * 6 + 3)
#define TPB 256
#define LUTC 32            // cells per axis over [-1,1]^2
#define LUTG (LUTC + 1)    // corner grid points per axis
#define LPAD (LUTC + 1)    // smem row pitch in float4 units (33: odd -> no column-walk conflicts)
#define GRID_PERSIST 1184  // 8 blocks/SM on 148 SMs; grid-stride tolerates any residency

// Folded fp32 parameters: per layer {a00, a01, c0, a10, a11, c1}; then {wo0, wo1, bo}
__device__ float g_fold[NPAR];
// Per-cell 2x2 corner quad: q.x=G[i][j] q.y=G[i][j+1] q.z=G[i+1][j] q.w=G[i+1][j+1]
__device__ float4 g_Q[LUTC * LUTC];

// Hardware tanh: one MUFU op.
__device__ __forceinline__ float htanh(float x) {
    float y;
    asm("tanh.approx.f32 %0, %1;" : "=f"(y) : "f"(x));
    return y;
}

// ONE prep kernel, one block, 1024 threads, ONE sync:
//   phase 1: parallel fold (33 threads; layer l needs only W[l],b[l],scale/shift[l-1])
//   phase 2: each thread owns ONE cell and evaluates its 4 corners as 4 interleaved
//            ILP chains (4x redundant vs corner-sharing, but latency-hidden and sync-free).
__global__ void __launch_bounds__(1024)
prep_kernel(const float* __restrict__ W, const float* __restrict__ b,
            const float* __restrict__ scale, const float* __restrict__ shift,
            const float* __restrict__ W_out, const float* __restrict__ b_out) {
    __shared__ float sf[NPAR];
    int t = threadIdx.x;

    // --- phase 1: fold. Layer 0 unclipped; layers 1..31 clip W,b to [-5,5].
    if (t < NLAYERS) {
        float sp0 = 1.0f, sp1 = 1.0f, shp0 = 0.0f, shp1 = 0.0f;
        if (t > 0) {
            sp0 = scale[(t - 1) * 2 + 0]; sp1 = scale[(t - 1) * 2 + 1];
            shp0 = shift[(t - 1) * 2 + 0]; shp1 = shift[(t - 1) * 2 + 1];
        }
        float w00 = W[t * 4 + 0], w01 = W[t * 4 + 1];
        float w10 = W[t * 4 + 2], w11 = W[t * 4 + 3];
        float bb0 = b[t * 2 + 0], bb1 = b[t * 2 + 1];
        if (t > 0) {
            w00 = fminf(fmaxf(w00, -5.0f), 5.0f);
            w01 = fminf(fmaxf(w01, -5.0f), 5.0f);
            w10 = fminf(fmaxf(w10, -5.0f), 5.0f);
            w11 = fminf(fmaxf(w11, -5.0f), 5.0f);
            bb0 = fminf(fmaxf(bb0, -5.0f), 5.0f);
            bb1 = fminf(fmaxf(bb1, -5.0f), 5.0f);
        }
        float f0 = w00 * sp0, f1 = w01 * sp1, f2 = w00 * shp0 + w01 * shp1 + bb0;
        float f3 = w10 * sp0, f4 = w11 * sp1, f5 = w10 * shp0 + w11 * shp1 + bb1;
        sf[t * 6 + 0] = f0; sf[t * 6 + 1] = f1; sf[t * 6 + 2] = f2;
        sf[t * 6 + 3] = f3; sf[t * 6 + 4] = f4; sf[t * 6 + 5] = f5;
        if (t == 0) {   // lookup kernel needs only layer-0 params
            g_fold[0] = f0; g_fold[1] = f1; g_fold[2] = f2;
            g_fold[3] = f3; g_fold[4] = f4; g_fold[5] = f5;
        }
    } else if (t == NLAYERS) {
        float sp0 = scale[(NLAYERS - 1) * 2 + 0], sp1 = scale[(NLAYERS - 1) * 2 + 1];
        float shp0 = shift[(NLAYERS - 1) * 2 + 0], shp1 = shift[(NLAYERS - 1) * 2 + 1];
        float wo0 = W_out[0], wo1 = W_out[1];
        sf[NLAYERS * 6 + 0] = wo0 * sp0;
        sf[NLAYERS * 6 + 1] = wo1 * sp1;
        sf[NLAYERS * 6 + 2] = wo0 * shp0 + wo1 * shp1 + b_out[0];
    }
    __syncthreads();

    // --- phase 2: one cell per thread; 4 corner evals as 4 ILP chains.
    int ci = t >> 5;          // cell row (t1)
    int cj = t & (LUTC - 1);  // cell col (t0)
    const float inv = 2.0f / (float)LUTC;
    float u0[4], u1[4];
    // corners: 0:(cj,ci) 1:(cj+1,ci) 2:(cj,ci+1) 3:(cj+1,ci+1)
#pragma unroll
    for (int c = 0; c < 4; ++c) {
        u0[c] = fmaf((float)(cj + (c & 1)), inv, -1.0f);
        u1[c] = fmaf((float)(ci + (c >> 1)), inv, -1.0f);
    }
#pragma unroll 1
    for (int l = 1; l < NLAYERS; ++l) {
        float a00 = sf[l * 6 + 0], a01 = sf[l * 6 + 1], c0 = sf[l * 6 + 2];
        float a10 = sf[l * 6 + 3], a11 = sf[l * 6 + 4], c1 = sf[l * 6 + 5];
#pragma unroll
        for (int c = 0; c < 4; ++c) {
            float z0 = fmaf(a00, u0[c], fmaf(a01, u1[c], c0));
            float z1 = fmaf(a10, u0[c], fmaf(a11, u1[c], c1));
            u0[c] = htanh(z0);
            u1[c] = htanh(z1);
        }
    }
    float wo0 = sf[NLAYERS * 6 + 0], wo1 = sf[NLAYERS * 6 + 1], bo = sf[NLAYERS * 6 + 2];
    float4 q;
    q.x = fmaf(wo0, u0[0], fmaf(wo1, u1[0], bo));
    q.y = fmaf(wo0, u0[1], fmaf(wo1, u1[1], bo));
    q.z = fmaf(wo0, u0[2], fmaf(wo1, u1[2], bo));
    q.w = fmaf(wo0, u0[3], fmaf(wo1, u1[3], bo));
    g_Q[t] = q;
}

// Persistent main kernel: layer 0 (fp32) + one LDS.128 bilinear lookup per row.
// Index math in float (trunc + one flat-index FFMA + single F2I); no clamps needed:
// tanh output is in [-1,1] and GS2 = GS*(1-eps) keeps gx in [eps, LUTC-eps].
__global__ void __launch_bounds__(TPB, 8)
lookup_kernel(const float4* __restrict__ x4, float2* __restrict__ out2, int n4) {
    __shared__ float4 squad[LUTC * LPAD];   // 32 x 33 x 16B = 16896 B

    for (int t = threadIdx.x; t < LUTC * LUTC; t += TPB) {
        squad[(t >> 5) * LPAD + (t & (LUTC - 1))] = g_Q[t];
    }
    const float a00 = g_fold[0], a01 = g_fold[1], c0 = g_fold[2];
    const float a10 = g_fold[3], a11 = g_fold[4], c1 = g_fold[5];
    __syncthreads();

    const float GS  = 0.5f * (float)LUTC;               // 16
    const float GS2 = GS * (1.0f - 9.5e-7f);            // keeps gx strictly inside [0, LUTC)
    const int stride = gridDim.x * TPB;
    int idx = blockIdx.x * TPB + threadIdx.x;

    // Main unrolled-by-4 grid-stride loop: 4 front-batched LDG.128 for MLP.
    for (; idx + 3 * stride < n4; idx += 4 * stride) {
        float4 v[4];
#pragma unroll
        for (int k = 0; k < 4; ++k) v[k] = x4[idx + k * stride];
#pragma unroll
        for (int k = 0; k < 4; ++k) {
            float res[2];
#pragma unroll
            for (int r = 0; r < 2; ++r) {
                float xi = (r == 0) ? v[k].x : v[k].z;
                float yi = (r == 0) ? v[k].y : v[k].w;
                float t0 = htanh(fmaf(a00, xi, fmaf(a01, yi, c0)));
                float t1 = htanh(fmaf(a10, xi, fmaf(a11, yi, c1)));
                float gx = fmaf(t0, GS2, GS);            // in (0, 32)
                float gy = fmaf(t1, GS2, GS);
                float gxf = truncf(gx);
                float gyf = truncf(gy);
                float fx = gx - gxf;
                float fy = gy - gyf;
                int cell = (int)fmaf(gyf, (float)LPAD, gxf);   // exact: small ints
                float4 q = squad[cell];                  // one LDS.128
                float top = fmaf(fx, q.y - q.x, q.x);
                float bot = fmaf(fx, q.w - q.z, q.z);
                res[r] = fmaf(fy, bot - top, top);
            }
            out2[idx + k * stride] = make_float2(res[0], res[1]);
        }
    }
    // Remainder
    for (; idx < n4; idx += stride) {
        float4 v = x4[idx];
        float res[2];
#pragma unroll
        for (int r = 0; r < 2; ++r) {
            float xi = (r == 0) ? v.x : v.z;
            float yi = (r == 0) ? v.y : v.w;
            float t0 = htanh(fmaf(a00, xi, fmaf(a01, yi, c0)));
            float t1 = htanh(fmaf(a10, xi, fmaf(a11, yi, c1)));
            float gx = fmaf(t0, GS2, GS);
            float gy = fmaf(t1, GS2, GS);
            float gxf = truncf(gx);
            float gyf = truncf(gy);
            float fx = gx - gxf;
            float fy = gy - gyf;
            int cell = (int)fmaf(gyf, (float)LPAD, gxf);
            float4 q = squad[cell];
            float top = fmaf(fx, q.y - q.x, q.x);
            float bot = fmaf(fx, q.w - q.z, q.z);
            res[r] = fmaf(fy, bot - top, top);
        }
        out2[idx] = make_float2(res[0], res[1]);
    }
}

extern "C" void kernel_launch(void* const* d_in, const int* in_sizes, int n_in,
                              void* d_out, int out_size) {
    const float* x     = (const float*)d_in[0];
    const float* W     = (const float*)d_in[1];
    const float* b     = (const float*)d_in[2];
    const float* scale = (const float*)d_in[3];
    const float* shift = (const float*)d_in[4];
    const float* W_out = (const float*)d_in[5];
    const float* b_out = (const float*)d_in[6];

    prep_kernel<<<1, 1024>>>(W, b, scale, shift, W_out, b_out);

    const int B  = in_sizes[0] / 2;   // rows
    const int n4 = B / 2;             // float4 count (2 rows per float4)

    lookup_kernel<<<GRID_PERSIST, TPB>>>((const float4*)x, (float2*)d_out, n4);
}

// round 13
// speedup vs baseline: 1.1738x; 1.1738x over previous
#include <cuda_runtime.h>
#include <stdint.h>

#define NLAYERS 32
#define NPAR (NLAYERS * 6 + 3)
#define TPB 256
#define LUTC 32            // cells per axis over [-1,1]^2
#define LPAD (LUTC + 1)    // smem row pitch in float4 units (33: odd -> no column-walk conflicts)
#define GRID_PERSIST 1184  // 8 blocks/SM on 148 SMs; grid-stride tolerates any residency
#define PREP_BLOCKS 8
#define PREP_TPB 128

// Folded fp32 layer-0 params + head (only what the lookup kernel reads)
__device__ float g_fold[6];
// Per-cell 2x2 corner quad: q.x=G[i][j] q.y=G[i][j+1] q.z=G[i+1][j] q.w=G[i+1][j+1]
__device__ float4 g_Q[LUTC * LUTC];

// Hardware tanh: one MUFU op.
__device__ __forceinline__ float htanh(float x) {
    float y;
    asm("tanh.approx.f32 %0, %1;" : "=f"(y) : "f"(x));
    return y;
}

// Multi-block prep: every block redundantly computes the fold (33 threads, ~400B reads,
// deterministic), then each thread evaluates ONE cell's 4 corners as 4 ILP chains.
// 8 blocks x 128 threads = 1024 cells; MUFU work is spread over 8 SMs (~1us each).
__global__ void __launch_bounds__(PREP_TPB)
prep_kernel(const float* __restrict__ W, const float* __restrict__ b,
            const float* __restrict__ scale, const float* __restrict__ shift,
            const float* __restrict__ W_out, const float* __restrict__ b_out) {
    __shared__ float sf[NPAR];
    int t = threadIdx.x;

    // --- fold (replicated per block). Layer 0 unclipped; layers 1..31 clip W,b to [-5,5].
    if (t < NLAYERS) {
        float sp0 = 1.0f, sp1 = 1.0f, shp0 = 0.0f, shp1 = 0.0f;
        if (t > 0) {
            sp0 = scale[(t - 1) * 2 + 0]; sp1 = scale[(t - 1) * 2 + 1];
            shp0 = shift[(t - 1) * 2 + 0]; shp1 = shift[(t - 1) * 2 + 1];
        }
        float w00 = W[t * 4 + 0], w01 = W[t * 4 + 1];
        float w10 = W[t * 4 + 2], w11 = W[t * 4 + 3];
        float bb0 = b[t * 2 + 0], bb1 = b[t * 2 + 1];
        if (t > 0) {
            w00 = fminf(fmaxf(w00, -5.0f), 5.0f);
            w01 = fminf(fmaxf(w01, -5.0f), 5.0f);
            w10 = fminf(fmaxf(w10, -5.0f), 5.0f);
            w11 = fminf(fmaxf(w11, -5.0f), 5.0f);
            bb0 = fminf(fmaxf(bb0, -5.0f), 5.0f);
            bb1 = fminf(fmaxf(bb1, -5.0f), 5.0f);
        }
        float f0 = w00 * sp0, f1 = w01 * sp1, f2 = w00 * shp0 + w01 * shp1 + bb0;
        float f3 = w10 * sp0, f4 = w11 * sp1, f5 = w10 * shp0 + w11 * shp1 + bb1;
        sf[t * 6 + 0] = f0; sf[t * 6 + 1] = f1; sf[t * 6 + 2] = f2;
        sf[t * 6 + 3] = f3; sf[t * 6 + 4] = f4; sf[t * 6 + 5] = f5;
        if (t == 0 && blockIdx.x == 0) {   // publish layer-0 params once
            g_fold[0] = f0; g_fold[1] = f1; g_fold[2] = f2;
            g_fold[3] = f3; g_fold[4] = f4; g_fold[5] = f5;
        }
    } else if (t == NLAYERS) {
        float sp0 = scale[(NLAYERS - 1) * 2 + 0], sp1 = scale[(NLAYERS - 1) * 2 + 1];
        float shp0 = shift[(NLAYERS - 1) * 2 + 0], shp1 = shift[(NLAYERS - 1) * 2 + 1];
        float wo0 = W_out[0], wo1 = W_out[1];
        sf[NLAYERS * 6 + 0] = wo0 * sp0;
        sf[NLAYERS * 6 + 1] = wo1 * sp1;
        sf[NLAYERS * 6 + 2] = wo0 * shp0 + wo1 * shp1 + b_out[0];
    }
    __syncthreads();

    // --- one cell per thread; 4 corner evals as 4 ILP chains.
    int cell = blockIdx.x * PREP_TPB + t;     // 0..1023
    int ci = cell >> 5;          // cell row (t1)
    int cj = cell & (LUTC - 1);  // cell col (t0)
    const float inv = 2.0f / (float)LUTC;
    float u0[4], u1[4];
    // corners: 0:(cj,ci) 1:(cj+1,ci) 2:(cj,ci+1) 3:(cj+1,ci+1)
#pragma unroll
    for (int c = 0; c < 4; ++c) {
        u0[c] = fmaf((float)(cj + (c & 1)), inv, -1.0f);
        u1[c] = fmaf((float)(ci + (c >> 1)), inv, -1.0f);
    }
#pragma unroll 1
    for (int l = 1; l < NLAYERS; ++l) {
        float a00 = sf[l * 6 + 0], a01 = sf[l * 6 + 1], c0 = sf[l * 6 + 2];
        float a10 = sf[l * 6 + 3], a11 = sf[l * 6 + 4], c1 = sf[l * 6 + 5];
#pragma unroll
        for (int c = 0; c < 4; ++c) {
            float z0 = fmaf(a00, u0[c], fmaf(a01, u1[c], c0));
            float z1 = fmaf(a10, u0[c], fmaf(a11, u1[c], c1));
            u0[c] = htanh(z0);
            u1[c] = htanh(z1);
        }
    }
    float wo0 = sf[NLAYERS * 6 + 0], wo1 = sf[NLAYERS * 6 + 1], bo = sf[NLAYERS * 6 + 2];
    float4 q;
    q.x = fmaf(wo0, u0[0], fmaf(wo1, u1[0], bo));
    q.y = fmaf(wo0, u0[1], fmaf(wo1, u1[1], bo));
    q.z = fmaf(wo0, u0[2], fmaf(wo1, u1[2], bo));
    q.w = fmaf(wo0, u0[3], fmaf(wo1, u1[3], bo));
    g_Q[cell] = q;
}

// Persistent main kernel: layer 0 (fp32) + one LDS.128 bilinear lookup per row.
// R10-proven inner loop (int indices; clamps ride the idle ALU pipe, F2I count minimal)
// + streaming cache hints on the once-touched x/out streams.
__global__ void __launch_bounds__(TPB, 8)
lookup_kernel(const float4* __restrict__ x4, float2* __restrict__ out2, int n4) {
    __shared__ float4 squad[LUTC * LPAD];   // 32 x 33 x 16B = 16896 B

    for (int t = threadIdx.x; t < LUTC * LUTC; t += TPB) {
        squad[(t >> 5) * LPAD + (t & (LUTC - 1))] = g_Q[t];
    }
    const float a00 = g_fold[0], a01 = g_fold[1], c0 = g_fold[2];
    const float a10 = g_fold[3], a11 = g_fold[4], c1 = g_fold[5];
    __syncthreads();

    const float GS = 0.5f * (float)LUTC;       // t in [-1,1] -> [0, LUTC]
    const int stride = gridDim.x * TPB;
    int idx = blockIdx.x * TPB + threadIdx.x;

    // Main unrolled-by-4 grid-stride loop: 4 front-batched LDG.128 for MLP.
    for (; idx + 3 * stride < n4; idx += 4 * stride) {
        float4 v[4];
#pragma unroll
        for (int k = 0; k < 4; ++k) v[k] = __ldcs(&x4[idx + k * stride]);   // evict-first stream
#pragma unroll
        for (int k = 0; k < 4; ++k) {
            float res[2];
#pragma unroll
            for (int r = 0; r < 2; ++r) {
                float xi = (r == 0) ? v[k].x : v[k].z;
                float yi = (r == 0) ? v[k].y : v[k].w;
                float t0 = htanh(fmaf(a00, xi, fmaf(a01, yi, c0)));
                float t1 = htanh(fmaf(a10, xi, fmaf(a11, yi, c1)));
                float gx = fminf(fmaxf(fmaf(t0, GS, GS), 0.0f), (float)LUTC);
                float gy = fminf(fmaxf(fmaf(t1, GS, GS), 0.0f), (float)LUTC);
                int ix = min((int)gx, LUTC - 1);
                int iy = min((int)gy, LUTC - 1);
                float fx = gx - (float)ix;
                float fy = gy - (float)iy;
                float4 q = squad[iy * LPAD + ix];          // one LDS.128
                float top = fmaf(fx, q.y - q.x, q.x);
                float bot = fmaf(fx, q.w - q.z, q.z);
                res[r] = fmaf(fy, bot - top, top);
            }
            __stcs(&out2[idx + k * stride], make_float2(res[0], res[1]));   // streaming store
        }
    }
    // Remainder
    for (; idx < n4; idx += stride) {
        float4 v = __ldcs(&x4[idx]);
        float res[2];
#pragma unroll
        for (int r = 0; r < 2; ++r) {
            float xi = (r == 0) ? v.x : v.z;
            float yi = (r == 0) ? v.y : v.w;
            float t0 = htanh(fmaf(a00, xi, fmaf(a01, yi, c0)));
            float t1 = htanh(fmaf(a10, xi, fmaf(a11, yi, c1)));
            float gx = fminf(fmaxf(fmaf(t0, GS, GS), 0.0f), (float)LUTC);
            float gy = fminf(fmaxf(fmaf(t1, GS, GS), 0.0f), (float)LUTC);
            int ix = min((int)gx, LUTC - 1);
            int iy = min((int)gy, LUTC - 1);
            float fx = gx - (float)ix;
            float fy = gy - (float)iy;
            float4 q = squad[iy * LPAD + ix];
            float top = fmaf(fx, q.y - q.x, q.x);
            float bot = fmaf(fx, q.w - q.z, q.z);
            res[r] = fmaf(fy, bot - top, top);
        }
        __stcs(&out2[idx], make_float2(res[0], res[1]));
    }
}

extern "C" void kernel_launch(void* const* d_in, const int* in_sizes, int n_in,
                              void* d_out, int out_size) {
    const float* x     = (const float*)d_in[0];
    const float* W     = (const float*)d_in[1];
    const float* b     = (const float*)d_in[2];
    const float* scale = (const float*)d_in[3];
    const float* shift = (const float*)d_in[4];
    const float* W_out = (const float*)d_in[5];
    const float* b_out = (const float*)d_in[6];

    prep_kernel<<<PREP_BLOCKS, PREP_TPB>>>(W, b, scale, shift, W_out, b_out);

    const int B  = in_sizes[0] / 2;   // rows
    const int n4 = B / 2;             // float4 count (2 rows per float4)

    lookup_kernel<<<GRID_PERSIST, TPB>>>((const float4*)x, (float2*)d_out, n4);
}